// round 1
// baseline (speedup 1.0000x reference)
#include <cuda_runtime.h>

#define Bb   4
#define Hh   176
#define Ww   200
#define CIN  128
#define COUT 256
#define NPTS (4096*64)
#define NCELL (Bb*Ww*Hh)
#define EPSf 1e-5f

// -------- scratch (device globals; no allocation allowed) --------
__device__ float g_dense[(size_t)NCELL*CIN];        // 72 MB scatter target
__device__ float g_out_dense[(size_t)NCELL*COUT];   // 144 MB per-cell outputs
__device__ float g_count[NCELL];
__device__ int   g_celllist[NCELL];
__device__ int   g_ncells;
__device__ float g_W2t[CIN*COUT];                   // W*gamma, transposed [c][o]
__device__ float g_gw[COUT];                        // sum_c W2[o,c]
__device__ float g_bias2[COUT];                     // sum_c beta[c]*W[o,c]

// -------- kernel 0: zero scratch --------
__global__ void k_zero() {
    int i = blockIdx.x * blockDim.x + threadIdx.x;
    int stride = gridDim.x * blockDim.x;
    float4 z = make_float4(0.f, 0.f, 0.f, 0.f);
    float4* d4 = (float4*)g_dense;
    const int n4 = NCELL * CIN / 4;
    for (int j = i; j < n4; j += stride) d4[j] = z;
    for (int j = i; j < NCELL; j += stride) g_count[j] = 0.f;
    if (i == 0) g_ncells = 0;
}

// -------- kernel 0b: fold layernorm affine into the weight --------
// blockIdx.x = output o (256 blocks), threadIdx.x = c (128 threads)
__global__ void k_prep(const float* __restrict__ lw,
                       const float* __restrict__ gamma,
                       const float* __restrict__ beta) {
    int o = blockIdx.x;
    int c = threadIdx.x;
    float w  = lw[o * CIN + c];
    float w2 = w * gamma[c];
    g_W2t[c * COUT + o] = w2;
    float gwv = w2;
    float b2  = w * beta[c];
    for (int s = 16; s > 0; s >>= 1) {
        gwv += __shfl_xor_sync(0xFFFFFFFFu, gwv, s);
        b2  += __shfl_xor_sync(0xFFFFFFFFu, b2,  s);
    }
    __shared__ float sg[4], sb[4];
    if ((c & 31) == 0) { sg[c >> 5] = gwv; sb[c >> 5] = b2; }
    __syncthreads();
    if (c == 0) {
        g_gw[o]    = sg[0] + sg[1] + sg[2] + sg[3];
        g_bias2[o] = sb[0] + sb[1] + sb[2] + sb[3];
    }
}

// -------- kernel 1: scatter-add (1 warp per point, float4 per lane) --------
__global__ void k_scatter(const float* __restrict__ feats,
                          const int* __restrict__ idx) {
    int g = blockIdx.x * blockDim.x + threadIdx.x;
    int p = g >> 5;
    int l = g & 31;
    if (p >= NPTS) return;
    int b = idx[3 * p + 0];
    int x = idx[3 * p + 1];
    int y = idx[3 * p + 2];
    if ((unsigned)x >= (unsigned)Hh || (unsigned)y >= (unsigned)Ww) return;
    int cell = (b * Ww + y) * Hh + x;
    float4 v = ((const float4*)(feats + (size_t)p * CIN))[l];
    float* dst = g_dense + (size_t)cell * CIN + 4 * l;
    atomicAdd(dst + 0, v.x);
    atomicAdd(dst + 1, v.y);
    atomicAdd(dst + 2, v.z);
    atomicAdd(dst + 3, v.w);
    if (l == 0) atomicAdd(&g_count[cell], 1.0f);
}

// -------- kernel 2: compact occupied cells --------
__global__ void k_compact() {
    int c = blockIdx.x * blockDim.x + threadIdx.x;
    if (c < NCELL && g_count[c] > 0.f) {
        int pos = atomicAdd(&g_ncells, 1);
        g_celllist[pos] = c;
    }
}

// -------- kernel 3: per-occupied-cell GEMM (FFMA, W resident in smem) --------
// Persistent blocks, 256 threads, tile = 16 cells x 256 outputs.
// smem: W2t[128][256] + x[16][128] + stats + gw/bias2 = 141,440 B  -> 1 CTA/SM
#define TILE_CELLS 16
#define SMEM_FLOATS (CIN*COUT + TILE_CELLS*CIN + 2*TILE_CELLS + 2*COUT)

__global__ void __launch_bounds__(256, 1) k_gemm() {
    extern __shared__ float sm[];
    float* Wsh = sm;                          // 32768
    float* xsh = Wsh + CIN * COUT;            // 2048
    float* sMu = xsh + TILE_CELLS * CIN;      // 16
    float* sRs = sMu + TILE_CELLS;            // 16
    float* sGw = sRs + TILE_CELLS;            // 256
    float* sB2 = sGw + COUT;                  // 256
    __shared__ int sCell[TILE_CELLS];

    int t = threadIdx.x;
    float4* Wsh4 = (float4*)Wsh;
    const float4* gW4 = (const float4*)g_W2t;
    for (int i = t; i < CIN * COUT / 4; i += 256) Wsh4[i] = gW4[i];
    for (int i = t; i < COUT; i += 256) { sGw[i] = g_gw[i]; sB2[i] = g_bias2[i]; }

    int ncell  = g_ncells;
    int ntiles = (ncell + TILE_CELLS - 1) / TILE_CELLS;

    int og = t & 63;       // float4 column group: outputs 4*og .. 4*og+3
    int cg = t >> 6;       // cell group 0..3 -> cells cg*4 .. cg*4+3
    int wrp = t >> 5, lane = t & 31;

    for (int tile = blockIdx.x; tile < ntiles; tile += gridDim.x) {
        __syncthreads();
        if (t < TILE_CELLS) {
            int ci = tile * TILE_CELLS + t;
            sCell[t] = (ci < ncell) ? g_celllist[ci] : -1;
        }
        __syncthreads();

        // load 16 x 128 f32 tile (512 float4)
        for (int i = t; i < TILE_CELLS * CIN / 4; i += 256) {
            int slot = i >> 5;       // 32 float4 per cell row
            int off  = i & 31;
            int cid  = sCell[slot];
            float4 v = make_float4(0.f, 0.f, 0.f, 0.f);
            if (cid >= 0) v = ((const float4*)(g_dense + (size_t)cid * CIN))[off];
            ((float4*)xsh)[i] = v;
        }
        __syncthreads();

        // per-cell stats: warp w handles cells 2w, 2w+1
        #pragma unroll
        for (int k = 0; k < 2; k++) {
            int cs = wrp * 2 + k;
            float s = 0.f, ss = 0.f;
            #pragma unroll
            for (int j = 0; j < 4; j++) {
                float v = xsh[cs * CIN + lane + 32 * j];
                s += v; ss += v * v;
            }
            for (int sft = 16; sft > 0; sft >>= 1) {
                s  += __shfl_xor_sync(0xFFFFFFFFu, s,  sft);
                ss += __shfl_xor_sync(0xFFFFFFFFu, ss, sft);
            }
            if (lane == 0) {
                float mu  = s * (1.f / CIN);
                float var = ss * (1.f / CIN) - mu * mu;
                sMu[cs] = mu;
                sRs[cs] = rsqrtf(var + EPSf);
            }
        }
        __syncthreads();

        // mainloop: 4 cells x 4 outputs per thread, 16 accumulators
        float4 acc[4];
        #pragma unroll
        for (int j = 0; j < 4; j++) acc[j] = make_float4(0.f, 0.f, 0.f, 0.f);
        const float4* xb4 = (const float4*)(xsh + cg * 4 * CIN);

        #pragma unroll 8
        for (int c4 = 0; c4 < CIN / 4; c4++) {
            float xa[4][4];
            *(float4*)xa[0] = xb4[0 * 32 + c4];
            *(float4*)xa[1] = xb4[1 * 32 + c4];
            *(float4*)xa[2] = xb4[2 * 32 + c4];
            *(float4*)xa[3] = xb4[3 * 32 + c4];
            #pragma unroll
            for (int q = 0; q < 4; q++) {
                float4 wv = Wsh4[(c4 * 4 + q) * (COUT / 4) + og];
                #pragma unroll
                for (int j = 0; j < 4; j++) {
                    float n = xa[j][q];
                    acc[j].x += wv.x * n;
                    acc[j].y += wv.y * n;
                    acc[j].z += wv.z * n;
                    acc[j].w += wv.w * n;
                }
            }
        }

        // epilogue: out = rstd*acc + (-rstd*mu)*gw + bias2
        float4 gw4 = ((float4*)sGw)[og];
        float4 b24 = ((float4*)sB2)[og];
        #pragma unroll
        for (int j = 0; j < 4; j++) {
            int cs  = cg * 4 + j;
            int cid = sCell[cs];
            if (cid >= 0) {
                float rs = sRs[cs];
                float mb = -rs * sMu[cs];
                float4 o;
                o.x = rs * acc[j].x + mb * gw4.x + b24.x;
                o.y = rs * acc[j].y + mb * gw4.y + b24.y;
                o.z = rs * acc[j].z + mb * gw4.z + b24.z;
                o.w = rs * acc[j].w + mb * gw4.w + b24.w;
                ((float4*)(g_out_dense + (size_t)cid * COUT))[og] = o;
            }
        }
    }
}

// -------- kernel 4: gather per point --------
__global__ void k_gather(const int* __restrict__ idx, float* __restrict__ out) {
    int g = blockIdx.x * blockDim.x + threadIdx.x;   // NPTS*64 threads
    int p = g >> 6;
    int f = g & 63;
    int b = idx[3 * p + 0];
    int x = idx[3 * p + 1];
    int y = idx[3 * p + 2];
    float4 v = make_float4(0.f, 0.f, 0.f, 0.f);
    if ((unsigned)x < (unsigned)Hh && (unsigned)y < (unsigned)Ww) {
        int cell = (b * Ww + y) * Hh + x;
        v = ((const float4*)(g_out_dense + (size_t)cell * COUT))[f];
    }
    ((float4*)out)[g] = v;
}

// -------- kernel 5: pass-through indices (numeric cast to f32) --------
__global__ void k_idx(const int* __restrict__ idx, float* __restrict__ out, int n) {
    int g = blockIdx.x * blockDim.x + threadIdx.x;
    if (g < n) out[g] = (float)idx[g];
}

extern "C" void kernel_launch(void* const* d_in, const int* in_sizes, int n_in,
                              void* d_out, int out_size) {
    const float* feats = (const float*)d_in[0];
    const int*   idx   = (const int*)d_in[1];
    const float* gamma = (const float*)d_in[2];
    const float* beta  = (const float*)d_in[3];
    const float* lw    = (const float*)d_in[4];
    float* out = (float*)d_out;

    const int smem_bytes = SMEM_FLOATS * 4;
    cudaFuncSetAttribute(k_gemm, cudaFuncAttributeMaxDynamicSharedMemorySize, smem_bytes);

    k_zero<<<17600, 256>>>();
    k_prep<<<COUT, CIN>>>(lw, gamma, beta);
    k_scatter<<<(NPTS * 32) / 256, 256>>>(feats, idx);
    k_compact<<<(NCELL + 255) / 256, 256>>>();
    k_gemm<<<148, 256, smem_bytes>>>();
    k_gather<<<(NPTS * 64) / 256, 256>>>(idx, out);

    long long tail = (long long)out_size - (long long)NPTS * COUT;
    if (tail > 0) {
        int n = (int)((tail < (long long)NPTS * 3) ? tail : (long long)NPTS * 3);
        k_idx<<<(n + 255) / 256, 256>>>(idx, out + (size_t)NPTS * COUT, n);
    }
}

// round 4
// speedup vs baseline: 1.3056x; 1.3056x over previous
#include <cuda_runtime.h>
#include <cstdint>

#define Bb   4
#define Hh   176
#define Ww   200
#define CIN  128
#define COUT 256
#define NPTS (4096*64)
#define NCELL (Bb*Ww*Hh)
#define EPSf 1e-5f

#define TILE_M 64           // cells per GEMM tile

// -------- scratch (device globals; no allocation allowed) --------
__device__ float g_dense[(size_t)NCELL*CIN];        // 72 MB scatter target
__device__ float g_out_dense[(size_t)NCELL*COUT];   // 144 MB per-cell outputs
__device__ float g_count[NCELL];
__device__ int   g_celllist[NCELL];
__device__ int   g_ncells;
__device__ float g_W2[COUT*CIN];                    // W*gamma (full fp32), [o][c]
__device__ float g_gw[COUT];                        // sum_c W2[o,c]
__device__ float g_bias2[COUT];                     // sum_c beta[c]*W[o,c]

// ======================= helpers =======================
__device__ __forceinline__ float to_tf32(float x) {
    float y; asm("cvt.rna.tf32.f32 %0, %1;" : "=f"(y) : "f"(x)); return y;
}

// D += A(tf32) * B(tf32);  a,b are .b32 regs holding tf32-rounded f32 bits
__device__ __forceinline__ void mma8(float* c, const uint32_t* a, const uint32_t* b) {
    asm volatile(
        "mma.sync.aligned.m16n8k8.row.col.f32.tf32.tf32.f32 "
        "{%0,%1,%2,%3}, {%4,%5,%6,%7}, {%8,%9}, {%0,%1,%2,%3};"
        : "+f"(c[0]), "+f"(c[1]), "+f"(c[2]), "+f"(c[3])
        : "r"(a[0]), "r"(a[1]), "r"(a[2]), "r"(a[3]), "r"(b[0]), "r"(b[1]));
}

// swizzled element index (in floats) for row-major [rows][128] tile:
// float4 slot = r*32 + ((k>>2) ^ (r&7)), word = k&3
__device__ __forceinline__ int swidx(int r, int f4, int w) {
    return (r * 32 + (f4 ^ (r & 7))) * 4 + w;
}

// ======================= small kernels =======================
__global__ void k_zero() {
    int i = blockIdx.x * blockDim.x + threadIdx.x;
    int stride = gridDim.x * blockDim.x;
    float4 z = make_float4(0.f, 0.f, 0.f, 0.f);
    float4* d4 = (float4*)g_dense;
    const int n4 = NCELL * CIN / 4;
    for (int j = i; j < n4; j += stride) d4[j] = z;
    for (int j = i; j < NCELL; j += stride) g_count[j] = 0.f;
    if (i == 0) g_ncells = 0;
}

// fold layernorm affine into weight (full fp32 now; GEMM is near-exact)
__global__ void k_prep(const float* __restrict__ lw,
                       const float* __restrict__ gamma,
                       const float* __restrict__ beta) {
    int o = blockIdx.x;
    int c = threadIdx.x;
    float w  = lw[o * CIN + c];
    float w2 = w * gamma[c];
    g_W2[o * CIN + c] = w2;
    float gwv = w2;
    float b2  = w * beta[c];
    for (int s = 16; s > 0; s >>= 1) {
        gwv += __shfl_xor_sync(0xFFFFFFFFu, gwv, s);
        b2  += __shfl_xor_sync(0xFFFFFFFFu, b2,  s);
    }
    __shared__ float sg[4], sb[4];
    if ((c & 31) == 0) { sg[c >> 5] = gwv; sb[c >> 5] = b2; }
    __syncthreads();
    if (c == 0) {
        g_gw[o]    = sg[0] + sg[1] + sg[2] + sg[3];
        g_bias2[o] = sb[0] + sb[1] + sb[2] + sb[3];
    }
}

// scatter-add: 1 warp per point, vectorized red.global.add.v4.f32 per lane
__global__ void k_scatter(const float* __restrict__ feats,
                          const int* __restrict__ idx) {
    int g = blockIdx.x * blockDim.x + threadIdx.x;
    int p = g >> 5;
    int l = g & 31;
    if (p >= NPTS) return;
    int b = idx[3 * p + 0];
    int x = idx[3 * p + 1];
    int y = idx[3 * p + 2];
    if ((unsigned)x >= (unsigned)Hh || (unsigned)y >= (unsigned)Ww) return;
    int cell = (b * Ww + y) * Hh + x;
    float4 v = ((const float4*)(feats + (size_t)p * CIN))[l];
    float* dst = g_dense + (size_t)cell * CIN + 4 * l;
    asm volatile("red.global.add.v4.f32 [%0], {%1, %2, %3, %4};"
                 :: "l"(dst), "f"(v.x), "f"(v.y), "f"(v.z), "f"(v.w) : "memory");
    if (l == 0) atomicAdd(&g_count[cell], 1.0f);
}

__global__ void k_compact() {
    int c = blockIdx.x * blockDim.x + threadIdx.x;
    if (c < NCELL && g_count[c] > 0.f) {
        int pos = atomicAdd(&g_ncells, 1);
        g_celllist[pos] = c;
    }
}

// ======================= mma.sync tf32x3 GEMM =======================
// smem map (bytes):
#define SM_AHI 0                     // 64x128 f32 swizzled          32768
#define SM_ALO 32768                 //                               32768
#define SM_BHI 65536                 // 128x128 f32 swizzled [n][k]   65536
#define SM_BLO 131072                //                               65536
#define SM_CL  196608                // 64 int
#define SM_RS  196864                // 64 f
#define SM_MB  197120                // 64 f  (= -rs*mu)
#define SM_GW  197376                // 128 f (this half)
#define SM_B2  197888                // 128 f
#define SMEM_TOTAL 198400

__global__ void __launch_bounds__(256, 1) k_gemm_mma() {
    extern __shared__ char sm[];
    float* Ah = (float*)(sm + SM_AHI);
    float* Al = (float*)(sm + SM_ALO);
    float* Bh = (float*)(sm + SM_BHI);
    float* Bl = (float*)(sm + SM_BLO);
    int*   sCl = (int*)(sm + SM_CL);
    float* sRs = (float*)(sm + SM_RS);
    float* sMb = (float*)(sm + SM_MB);
    float* sGw = (float*)(sm + SM_GW);
    float* sB2 = (float*)(sm + SM_B2);

    int t = threadIdx.x;
    int lane = t & 31, wid = t >> 5;
    int grp = lane >> 2, tg = lane & 3;
    int warp_m = wid >> 2;            // 0..1
    int warp_n = wid & 3;             // 0..3
    int mbase = warp_m * 32;
    int nbase = warp_n * 32;

    int ncell  = g_ncells;
    int ntiles = (ncell + TILE_M - 1) / TILE_M;

    // A loader mapping: cell m = t>>2, quarter q = t&3 (f4 cols q*8..q*8+7)
    int lm = t >> 2, lq = t & 3;

    for (int h = 0; h < 2; h++) {
        __syncthreads();
        // ---- load B (this half's 128 outputs), hi/lo split, swizzled [n][k] ----
        for (int i = t; i < 128 * 32; i += 256) {
            int n = i >> 5, f4 = i & 31;
            float4 v = ((const float4*)g_W2)[(h * 128 + n) * 32 + f4];
            float4 hi = make_float4(to_tf32(v.x), to_tf32(v.y), to_tf32(v.z), to_tf32(v.w));
            float4 lo = make_float4(to_tf32(v.x - hi.x), to_tf32(v.y - hi.y),
                                    to_tf32(v.z - hi.z), to_tf32(v.w - hi.w));
            int slot = n * 32 + (f4 ^ (n & 7));
            ((float4*)Bh)[slot] = hi;
            ((float4*)Bl)[slot] = lo;
        }
        for (int i = t; i < 128; i += 256) {
            sGw[i] = g_gw[h * 128 + i];
            sB2[i] = g_bias2[h * 128 + i];
        }
        __syncthreads();

        for (int tile = blockIdx.x; tile < ntiles; tile += gridDim.x) {
            __syncthreads();
            if (t < TILE_M) {
                int ci = tile * TILE_M + t;
                sCl[t] = (ci < ncell) ? g_celllist[ci] : -1;
            }
            __syncthreads();

            // ---- A tile load + stats + hi/lo split + swizzled store ----
            {
                int cid = sCl[lm];
                const float4* src = (cid >= 0)
                    ? (const float4*)(g_dense + (size_t)cid * CIN) : nullptr;
                float s = 0.f, ss = 0.f;
                #pragma unroll
                for (int j = 0; j < 8; j++) {
                    int f4 = lq * 8 + j;
                    float4 v = src ? src[f4] : make_float4(0.f, 0.f, 0.f, 0.f);
                    s  += v.x + v.y + v.z + v.w;
                    ss += v.x*v.x + v.y*v.y + v.z*v.z + v.w*v.w;
                    float4 hi = make_float4(to_tf32(v.x), to_tf32(v.y), to_tf32(v.z), to_tf32(v.w));
                    float4 lo = make_float4(to_tf32(v.x - hi.x), to_tf32(v.y - hi.y),
                                            to_tf32(v.z - hi.z), to_tf32(v.w - hi.w));
                    int slot = lm * 32 + (f4 ^ (lm & 7));
                    ((float4*)Ah)[slot] = hi;
                    ((float4*)Al)[slot] = lo;
                }
                s  += __shfl_xor_sync(0xFFFFFFFFu, s,  1);
                ss += __shfl_xor_sync(0xFFFFFFFFu, ss, 1);
                s  += __shfl_xor_sync(0xFFFFFFFFu, s,  2);
                ss += __shfl_xor_sync(0xFFFFFFFFu, ss, 2);
                if (lq == 0) {
                    float mu  = s * (1.f / CIN);
                    float var = ss * (1.f / CIN) - mu * mu;
                    float rs  = rsqrtf(var + EPSf);
                    sRs[lm] = rs;
                    sMb[lm] = -rs * mu;
                }
            }
            __syncthreads();

            // ---- mainloop: 16 k-steps, tf32x3 ----
            float acc[2][4][4];
            #pragma unroll
            for (int a = 0; a < 2; a++)
                #pragma unroll
                for (int b = 0; b < 4; b++)
                    #pragma unroll
                    for (int c = 0; c < 4; c++) acc[a][b][c] = 0.f;

            int am0 = mbase + grp;          // rows for mf=0: am0, am0+8
            const uint32_t* Ahu = (const uint32_t*)Ah;
            const uint32_t* Alu = (const uint32_t*)Al;
            const uint32_t* Bhu = (const uint32_t*)Bh;
            const uint32_t* Blu = (const uint32_t*)Bl;

            #pragma unroll 4
            for (int ks = 0; ks < 16; ks++) {
                int f4a = 2 * ks, f4b = 2 * ks + 1;
                uint32_t ah[2][4], al[2][4];
                #pragma unroll
                for (int mf = 0; mf < 2; mf++) {
                    int r0 = am0 + mf * 16, r1 = r0 + 8;
                    ah[mf][0] = Ahu[swidx(r0, f4a, tg)];
                    ah[mf][1] = Ahu[swidx(r1, f4a, tg)];
                    ah[mf][2] = Ahu[swidx(r0, f4b, tg)];
                    ah[mf][3] = Ahu[swidx(r1, f4b, tg)];
                    al[mf][0] = Alu[swidx(r0, f4a, tg)];
                    al[mf][1] = Alu[swidx(r1, f4a, tg)];
                    al[mf][2] = Alu[swidx(r0, f4b, tg)];
                    al[mf][3] = Alu[swidx(r1, f4b, tg)];
                }
                #pragma unroll
                for (int nf = 0; nf < 4; nf++) {
                    int n0 = nbase + nf * 8 + grp;
                    uint32_t bh[2], bl[2];
                    bh[0] = Bhu[swidx(n0, f4a, tg)];
                    bh[1] = Bhu[swidx(n0, f4b, tg)];
                    bl[0] = Blu[swidx(n0, f4a, tg)];
                    bl[1] = Blu[swidx(n0, f4b, tg)];
                    mma8(acc[0][nf], ah[0], bh);
                    mma8(acc[1][nf], ah[1], bh);
                    mma8(acc[0][nf], al[0], bh);
                    mma8(acc[1][nf], al[1], bh);
                    mma8(acc[0][nf], ah[0], bl);
                    mma8(acc[1][nf], ah[1], bl);
                }
            }

            // ---- epilogue: affine + direct STG.64 ----
            #pragma unroll
            for (int mf = 0; mf < 2; mf++) {
                int r0 = am0 + mf * 16, r1 = r0 + 8;
                int cid0 = sCl[r0], cid1 = sCl[r1];
                float rs0 = sRs[r0], mb0 = sMb[r0];
                float rs1 = sRs[r1], mb1 = sMb[r1];
                #pragma unroll
                for (int nf = 0; nf < 4; nf++) {
                    int n0 = nbase + nf * 8 + 2 * tg;
                    float gw0 = sGw[n0], gw1 = sGw[n0 + 1];
                    float b20 = sB2[n0], b21 = sB2[n0 + 1];
                    if (cid0 >= 0) {
                        float2 v;
                        v.x = rs0 * acc[mf][nf][0] + mb0 * gw0 + b20;
                        v.y = rs0 * acc[mf][nf][1] + mb0 * gw1 + b21;
                        *(float2*)(g_out_dense + (size_t)cid0 * COUT + h * 128 + n0) = v;
                    }
                    if (cid1 >= 0) {
                        float2 v;
                        v.x = rs1 * acc[mf][nf][2] + mb1 * gw0 + b20;
                        v.y = rs1 * acc[mf][nf][3] + mb1 * gw1 + b21;
                        *(float2*)(g_out_dense + (size_t)cid1 * COUT + h * 128 + n0) = v;
                    }
                }
            }
        }
    }
}

// ======================= gather =======================
__global__ void k_gather(const int* __restrict__ idx, float* __restrict__ out) {
    int g = blockIdx.x * blockDim.x + threadIdx.x;   // NPTS*64 threads
    int p = g >> 6;
    int f = g & 63;
    int b = idx[3 * p + 0];
    int x = idx[3 * p + 1];
    int y = idx[3 * p + 2];
    float4 v = make_float4(0.f, 0.f, 0.f, 0.f);
    if ((unsigned)x < (unsigned)Hh && (unsigned)y < (unsigned)Ww) {
        int cell = (b * Ww + y) * Hh + x;
        v = ((const float4*)(g_out_dense + (size_t)cell * COUT))[f];
    }
    ((float4*)out)[g] = v;
}

__global__ void k_idx(const int* __restrict__ idx, float* __restrict__ out, int n) {
    int g = blockIdx.x * blockDim.x + threadIdx.x;
    if (g < n) out[g] = (float)idx[g];
}

extern "C" void kernel_launch(void* const* d_in, const int* in_sizes, int n_in,
                              void* d_out, int out_size) {
    const float* feats = (const float*)d_in[0];
    const int*   idx   = (const int*)d_in[1];
    const float* gamma = (const float*)d_in[2];
    const float* beta  = (const float*)d_in[3];
    const float* lw    = (const float*)d_in[4];
    float* out = (float*)d_out;

    cudaFuncSetAttribute(k_gemm_mma, cudaFuncAttributeMaxDynamicSharedMemorySize, SMEM_TOTAL);

    k_zero<<<17600, 256>>>();
    k_prep<<<COUT, CIN>>>(lw, gamma, beta);
    k_scatter<<<(NPTS * 32) / 256, 256>>>(feats, idx);
    k_compact<<<(NCELL + 255) / 256, 256>>>();
    k_gemm_mma<<<148, 256, SMEM_TOTAL>>>();
    k_gather<<<(NPTS * 64) / 256, 256>>>(idx, out);

    long long tail = (long long)out_size - (long long)NPTS * COUT;
    if (tail > 0) {
        int n = (int)((tail < (long long)NPTS * 3) ? tail : (long long)NPTS * 3);
        k_idx<<<(n + 255) / 256, 256>>>(idx, out + (size_t)NPTS * COUT, n);
    }
}